// round 6
// baseline (speedup 1.0000x reference)
#include <cuda_runtime.h>
#include <cuda_bf16.h>
#include <math.h>

#define Bn     64
#define Vn     16384
#define En     524288
#define Kc     6
#define F1     32
#define POOLn  8
#define VG     (Vn / POOLn)       // 2048
#define FC1FIN (F1 * VG)          // 65536
#define FC1F   512
#define FC2F   512
#define NN1F   1024
#define NN2F   512
#define OUTC   10

// ---------------- scratch (device globals; no runtime allocation) ----------
__device__ __align__(16) float g_xs[6 * Vn * Bn];        // Chebyshev basis, [k][v][b]
__device__ __align__(16) float g_pooled[FC1FIN * Bn];    // [i][b]
__device__ __align__(16) float g_yfc1[FC1F * Bn];
__device__ __align__(16) float g_hid[FC1F * Bn];
__device__ __align__(16) float g_yfc2[FC2F * Bn];
__device__ __align__(16) float g_xd[FC2F * Bn];
__device__ __align__(16) float g_yfc3[Vn * Bn];
__device__ __align__(16) float g_ynn1[NN1F * Bn];
__device__ __align__(16) float g_xn1[NN1F * Bn];
__device__ __align__(16) float g_ynn2[NN2F * Bn];
__device__ __align__(16) float g_xn2[NN2F * Bn];
__device__ int  g_rowptr[Vn + 1];
__device__ int  g_cursor[Vn];
__device__ __align__(8) int2 g_csr[En];                  // (col, val bits)

// ---------------- packed f32x2 helpers (sm_103a) ----------------------------
__device__ __forceinline__ unsigned long long dup2(float v) {
    unsigned long long r;
    asm("mov.b64 %0, {%1, %1};" : "=l"(r) : "f"(v));
    return r;
}
#define FFMA2(acc, w, x) asm("fma.rn.f32x2 %0, %1, %2, %0;" : "+l"(acc) : "l"(w), "l"(x))

// ---------------- transpose x_in [64][V] -> [V][64] ------------------------
__global__ void k_transpose_in(const float* __restrict__ xin, float* __restrict__ xout) {
    __shared__ float t[32][33];
    int v0 = blockIdx.x * 32, b0 = blockIdx.y * 32;
    int tx = threadIdx.x, ty = threadIdx.y;
    #pragma unroll
    for (int j = 0; j < 32; j += 8)
        t[ty + j][tx] = xin[(size_t)(b0 + ty + j) * Vn + v0 + tx];
    __syncthreads();
    #pragma unroll
    for (int j = 0; j < 32; j += 8)
        xout[(size_t)(v0 + ty + j) * Bn + b0 + tx] = t[tx][ty + j];
}

// ---------------- CSR build -------------------------------------------------
__global__ void k_hist(const int* __restrict__ rows) {
    int e = blockIdx.x * 256 + threadIdx.x;
    if (e < En) atomicAdd(&g_rowptr[rows[e] + 1], 1);
}

__global__ void k_scan() {   // 1 block, 1024 threads, V = 1024*16
    __shared__ int sm[1024];
    int tid = threadIdx.x;
    int loc[16];
    int base = 1 + tid * 16;
    int s = 0;
    #pragma unroll
    for (int j = 0; j < 16; j++) { loc[j] = g_rowptr[base + j]; s += loc[j]; }
    sm[tid] = s;
    __syncthreads();
    for (int off = 1; off < 1024; off <<= 1) {
        int v = (tid >= off) ? sm[tid - off] : 0;
        __syncthreads();
        sm[tid] += v;
        __syncthreads();
    }
    int run = sm[tid] - s;   // exclusive prefix of this thread's chunk
    #pragma unroll
    for (int j = 0; j < 16; j++) { run += loc[j]; g_rowptr[base + j] = run; }
}

__global__ void k_scatter(const int* __restrict__ rows, const int* __restrict__ cols,
                          const float* __restrict__ vals) {
    int e = blockIdx.x * 256 + threadIdx.x;
    if (e < En) {
        int r = rows[e];
        int p = g_rowptr[r] + atomicAdd(&g_cursor[r], 1);
        g_csr[p] = make_int2(cols[e], __float_as_int(vals[e]));
    }
}

// ---------------- SpMM: out = alpha * (L @ x) + beta * prev ----------------
// warp per row; lane handles 2 batch columns (float2)
__global__ void k_spmm(const float* __restrict__ xin, const float* __restrict__ prev,
                       float* __restrict__ xout, float alpha, float beta) {
    int warp = threadIdx.x >> 5, lane = threadIdx.x & 31;
    int row = blockIdx.x * 8 + warp;
    int s = g_rowptr[row], e = g_rowptr[row + 1];
    const float2* __restrict__ xin2 = (const float2*)xin;
    float2 acc = make_float2(0.f, 0.f);
    int i = s;
    for (; i + 1 < e; i += 2) {
        int2 cv0 = g_csr[i];
        int2 cv1 = g_csr[i + 1];
        float2 x0 = xin2[(size_t)cv0.x * 32 + lane];
        float2 x1 = xin2[(size_t)cv1.x * 32 + lane];
        float v0 = __int_as_float(cv0.y), v1 = __int_as_float(cv1.y);
        acc.x += v0 * x0.x; acc.y += v0 * x0.y;
        acc.x += v1 * x1.x; acc.y += v1 * x1.y;
    }
    if (i < e) {
        int2 cv = g_csr[i];
        float2 xv = xin2[(size_t)cv.x * 32 + lane];
        float v = __int_as_float(cv.y);
        acc.x += v * xv.x; acc.y += v * xv.y;
    }
    size_t o = (size_t)row * 32 + lane;
    float2 pv = ((const float2*)prev)[o];
    float2 r;
    r.x = alpha * acc.x + beta * pv.x;
    r.y = alpha * acc.y + beta * pv.y;
    ((float2*)xout)[o] = r;
}

// ---------------- fused cheby-combine + relu + maxpool ----------------------
// block (64,4): x = batch, y = local vgroup; writes pooled[(vg*32+f)][b]
__global__ void k_chebypool(const float* __restrict__ w, const float* __restrict__ bias) {
    __shared__ float sw[F1 * Kc];
    __shared__ float sb[F1];
    int tid = threadIdx.y * 64 + threadIdx.x;
    if (tid < F1 * Kc) sw[tid] = w[tid];
    if (tid >= F1 * Kc && tid < F1 * Kc + F1) sb[tid - F1 * Kc] = bias[tid - F1 * Kc];
    __syncthreads();
    int b  = threadIdx.x;
    int vg = blockIdx.x * 4 + threadIdx.y;
    float mx[F1];
    #pragma unroll
    for (int f = 0; f < F1; f++) mx[f] = -INFINITY;
    int v0 = vg * POOLn;
    for (int v = v0; v < v0 + POOLn; v++) {
        float t[Kc];
        #pragma unroll
        for (int k = 0; k < Kc; k++)
            t[k] = g_xs[(size_t)k * Vn * Bn + (size_t)v * Bn + b];
        #pragma unroll
        for (int f = 0; f < F1; f++) {
            float s = sb[f];
            #pragma unroll
            for (int k = 0; k < Kc; k++) s += t[k] * sw[f * Kc + k];
            mx[f] = fmaxf(mx[f], s);
        }
    }
    #pragma unroll
    for (int f = 0; f < F1; f++)
        g_pooled[((size_t)vg * F1 + f) * Bn + b] = fmaxf(mx[f], 0.f);
}

// ---------------- fp32 GEMM via packed FFMA2: Y[n][b] += sum_k X[k][b]*W[n][k]
// grid (N/64, S), block 256; split-K partials accumulated with atomicAdd.
// Inner loop: 3x LDS.128 + 8x fma.rn.f32x2 per k  (32 MACs / 11 issues).
__global__ __launch_bounds__(256)
void k_gemm(const float* __restrict__ X, const float* __restrict__ W,
            float* __restrict__ Y, int N, int K, int kspan) {
    const int KC = 32;
    __shared__ __align__(16) float Xs[KC * 64];
    __shared__ __align__(16) unsigned long long Ws2[KC][68];   // (w,w) duplicated pairs
    int tid = threadIdx.x;
    int n0 = blockIdx.x * 64;
    int k0 = blockIdx.y * kspan;
    int k1 = min(K, k0 + kspan);
    int bg = tid & 15;          // b = bg*4 (two packed pairs)
    int ng = tid >> 4;          // n = ng*4
    unsigned long long a00=0,a01=0,a10=0,a11=0,a20=0,a21=0,a30=0,a31=0;
    // W-tile loader geometry: 64 rows x 8 float4-groups = 512 float4, 2/thread
    int wrow = tid >> 2;            // 0..63
    int wj0  = (tid & 3) * 4;       // k-offset 0,4,8,12 (second pass +16)
    for (int kb = k0; kb < k1; kb += KC) {
        __syncthreads();
        {   // X chunk: contiguous 8KB, 512 float4, 2/thread
            const float4* Xg = (const float4*)(X + (size_t)kb * 64);
            float4* Xs4 = (float4*)Xs;
            Xs4[tid]       = Xg[tid];
            Xs4[tid + 256] = Xg[tid + 256];
        }
        {   // W chunk: 64 rows x 32 k, store transposed [k][n] with (w,w) dup
            #pragma unroll
            for (int h = 0; h < 2; h++) {
                int jj = wj0 + h * 16;
                float4 wv = *(const float4*)(W + (size_t)(n0 + wrow) * K + kb + jj);
                Ws2[jj + 0][wrow] = dup2(wv.x);
                Ws2[jj + 1][wrow] = dup2(wv.y);
                Ws2[jj + 2][wrow] = dup2(wv.z);
                Ws2[jj + 3][wrow] = dup2(wv.w);
            }
        }
        __syncthreads();
        #pragma unroll
        for (int k = 0; k < KC; k++) {
            ulonglong2 xv  = *(const ulonglong2*)(Xs + k * 64 + bg * 4);
            ulonglong2 w01 = *(const ulonglong2*)(&Ws2[k][ng * 4]);
            ulonglong2 w23 = *(const ulonglong2*)(&Ws2[k][ng * 4 + 2]);
            FFMA2(a00, w01.x, xv.x); FFMA2(a01, w01.x, xv.y);
            FFMA2(a10, w01.y, xv.x); FFMA2(a11, w01.y, xv.y);
            FFMA2(a20, w23.x, xv.x); FFMA2(a21, w23.x, xv.y);
            FFMA2(a30, w23.y, xv.x); FFMA2(a31, w23.y, xv.y);
        }
    }
    float* y = Y + (size_t)(n0 + ng * 4) * 64 + bg * 4;
    union { unsigned long long u; float2 f; } c;
    c.u = a00; atomicAdd(y + 0*64 + 0, c.f.x); atomicAdd(y + 0*64 + 1, c.f.y);
    c.u = a01; atomicAdd(y + 0*64 + 2, c.f.x); atomicAdd(y + 0*64 + 3, c.f.y);
    c.u = a10; atomicAdd(y + 1*64 + 0, c.f.x); atomicAdd(y + 1*64 + 1, c.f.y);
    c.u = a11; atomicAdd(y + 1*64 + 2, c.f.x); atomicAdd(y + 1*64 + 3, c.f.y);
    c.u = a20; atomicAdd(y + 2*64 + 0, c.f.x); atomicAdd(y + 2*64 + 1, c.f.y);
    c.u = a21; atomicAdd(y + 2*64 + 2, c.f.x); atomicAdd(y + 2*64 + 3, c.f.y);
    c.u = a30; atomicAdd(y + 3*64 + 0, c.f.x); atomicAdd(y + 3*64 + 1, c.f.y);
    c.u = a31; atomicAdd(y + 3*64 + 2, c.f.x); atomicAdd(y + 3*64 + 3, c.f.y);
}

// ---------------- epilogues -------------------------------------------------
__global__ void k_bias_act(const float* __restrict__ Y, const float* __restrict__ bias,
                           float* __restrict__ dst, int total, int relu) {
    int i = blockIdx.x * 256 + threadIdx.x;
    if (i < total) {
        int n = i >> 6;
        float v = Y[i] + bias[n];
        if (relu) v = fmaxf(v, 0.f);
        dst[i] = v;
    }
}

__global__ void k_copy_hidden(const float* __restrict__ hid, float* __restrict__ out2) {
    int i = blockIdx.x * 256 + threadIdx.x;
    if (i < FC1F * Bn) {
        int n = i >> 6, b = i & 63;
        out2[b * FC1F + n] = hid[i];
    }
}

// fc3 epilogue: add bias + transpose [v][b] -> out[b][v]
__global__ void k_fc3_out(const float* __restrict__ Y, const float* __restrict__ bias,
                          float* __restrict__ out) {
    __shared__ float t[32][33];
    int v0 = blockIdx.x * 32, b0 = blockIdx.y * 32;
    int tx = threadIdx.x, ty = threadIdx.y;
    #pragma unroll
    for (int j = 0; j < 32; j += 8)
        t[ty + j][tx] = Y[(size_t)(v0 + ty + j) * 64 + b0 + tx] + bias[v0 + ty + j];
    __syncthreads();
    #pragma unroll
    for (int j = 0; j < 32; j += 8)
        out[(size_t)(b0 + ty + j) * Vn + v0 + tx] = t[tx][ty + j];
}

// ---------------- fused sum2 + log_softmax ----------------------------------
__global__ void k_sum2(const float* __restrict__ hid, const float* __restrict__ xn2,
                       const float* __restrict__ w, const float* __restrict__ bias,
                       float* __restrict__ outlp) {
    int b = blockIdx.x, tid = threadIdx.x;
    float acc[OUTC];
    #pragma unroll
    for (int n = 0; n < OUTC; n++) acc[n] = 0.f;
    for (int k = tid; k < FC1F + NN2F; k += 256) {
        float xv = (k < FC1F) ? hid[k * 64 + b] : xn2[(k - FC1F) * 64 + b];
        #pragma unroll
        for (int n = 0; n < OUTC; n++) acc[n] += xv * w[n * (FC1F + NN2F) + k];
    }
    #pragma unroll
    for (int off = 16; off; off >>= 1)
        #pragma unroll
        for (int n = 0; n < OUTC; n++)
            acc[n] += __shfl_down_sync(0xffffffffu, acc[n], off);
    __shared__ float red[8][OUTC];
    int lane = tid & 31, wp = tid >> 5;
    if (lane == 0)
        #pragma unroll
        for (int n = 0; n < OUTC; n++) red[wp][n] = acc[n];
    __syncthreads();
    if (tid == 0) {
        float z[OUTC];
        #pragma unroll
        for (int n = 0; n < OUTC; n++) {
            float s = bias[n];
            #pragma unroll
            for (int w8 = 0; w8 < 8; w8++) s += red[w8][n];
            z[n] = s;
        }
        float m = z[0];
        #pragma unroll
        for (int n = 1; n < OUTC; n++) m = fmaxf(m, z[n]);
        float se = 0.f;
        #pragma unroll
        for (int n = 0; n < OUTC; n++) se += expf(z[n] - m);
        float l = m + logf(se);
        #pragma unroll
        for (int n = 0; n < OUTC; n++) outlp[b * OUTC + n] = z[n] - l;
    }
}

// ---------------- launcher --------------------------------------------------
extern "C" void kernel_launch(void* const* d_in, const int* in_sizes, int n_in,
                              void* d_out, int out_size) {
    const float* x_in   = (const float*)d_in[0];
    const float* L_vals = (const float*)d_in[1];
    const float* cl1_w  = (const float*)d_in[2];
    const float* cl1_b  = (const float*)d_in[3];
    const float* fc1_w  = (const float*)d_in[4];
    const float* fc1_b  = (const float*)d_in[5];
    const float* fc2_w  = (const float*)d_in[6];
    const float* fc2_b  = (const float*)d_in[7];
    const float* fc3_w  = (const float*)d_in[8];
    const float* fc3_b  = (const float*)d_in[9];
    const float* nn1_w  = (const float*)d_in[10];
    const float* nn1_b  = (const float*)d_in[11];
    const float* nn2_w  = (const float*)d_in[12];
    const float* nn2_b  = (const float*)d_in[13];
    const float* sum2_w = (const float*)d_in[14];
    const float* sum2_b = (const float*)d_in[15];
    const int*   L_rows = (const int*)d_in[16];
    const int*   L_cols = (const int*)d_in[17];

    float* out = (float*)d_out;
    float* out_dec = out;                       // [64][16384]
    float* out_hid = out + (size_t)Bn * Vn;     // [64][512]
    float* out_lp  = out_hid + Bn * FC1F;       // [64][10]

    void *p_xs, *p_pooled, *p_yfc1, *p_hid, *p_yfc2, *p_xd, *p_yfc3;
    void *p_ynn1, *p_xn1, *p_ynn2, *p_xn2, *p_rowptr, *p_cursor;
    cudaGetSymbolAddress(&p_xs, g_xs);
    cudaGetSymbolAddress(&p_pooled, g_pooled);
    cudaGetSymbolAddress(&p_yfc1, g_yfc1);
    cudaGetSymbolAddress(&p_hid, g_hid);
    cudaGetSymbolAddress(&p_yfc2, g_yfc2);
    cudaGetSymbolAddress(&p_xd, g_xd);
    cudaGetSymbolAddress(&p_yfc3, g_yfc3);
    cudaGetSymbolAddress(&p_ynn1, g_ynn1);
    cudaGetSymbolAddress(&p_xn1, g_xn1);
    cudaGetSymbolAddress(&p_ynn2, g_ynn2);
    cudaGetSymbolAddress(&p_xn2, g_xn2);
    cudaGetSymbolAddress(&p_rowptr, g_rowptr);
    cudaGetSymbolAddress(&p_cursor, g_cursor);

    float* xs     = (float*)p_xs;
    float* pooled = (float*)p_pooled;
    const size_t VB = (size_t)Vn * Bn;

    // CSR build + input transpose
    cudaMemsetAsync(p_rowptr, 0, (Vn + 1) * sizeof(int));
    cudaMemsetAsync(p_cursor, 0, Vn * sizeof(int));
    k_transpose_in<<<dim3(Vn / 32, Bn / 32), dim3(32, 8)>>>(x_in, xs);
    k_hist<<<En / 256, 256>>>(L_rows);
    k_scan<<<1, 1024>>>();
    k_scatter<<<En / 256, 256>>>(L_rows, L_cols, L_vals);

    // Chebyshev recursion: xs[k] = 2 L xs[k-1] - xs[k-2]
    k_spmm<<<Vn / 8, 256>>>(xs,          xs,          xs + VB,     1.f,  0.f);
    k_spmm<<<Vn / 8, 256>>>(xs + VB,     xs,          xs + 2 * VB, 2.f, -1.f);
    k_spmm<<<Vn / 8, 256>>>(xs + 2 * VB, xs + VB,     xs + 3 * VB, 2.f, -1.f);
    k_spmm<<<Vn / 8, 256>>>(xs + 3 * VB, xs + 2 * VB, xs + 4 * VB, 2.f, -1.f);
    k_spmm<<<Vn / 8, 256>>>(xs + 4 * VB, xs + 3 * VB, xs + 5 * VB, 2.f, -1.f);

    // combine + relu + maxpool -> pooled [65536][64]
    k_chebypool<<<VG / 4, dim3(64, 4)>>>(cl1_w, cl1_b);

    // fc1 -> hidden
    cudaMemsetAsync(p_yfc1, 0, (size_t)FC1F * Bn * sizeof(float));
    k_gemm<<<dim3(FC1F / 64, 64), 256>>>(pooled, fc1_w, (float*)p_yfc1, FC1F, FC1FIN, 1024);
    k_bias_act<<<(FC1F * Bn + 255) / 256, 256>>>((float*)p_yfc1, fc1_b, (float*)p_hid, FC1F * Bn, 1);
    k_copy_hidden<<<(FC1F * Bn + 255) / 256, 256>>>((float*)p_hid, out_hid);

    // nn branch (input = x_in^T = xs[0])
    cudaMemsetAsync(p_ynn1, 0, (size_t)NN1F * Bn * sizeof(float));
    k_gemm<<<dim3(NN1F / 64, 16), 256>>>(xs, nn1_w, (float*)p_ynn1, NN1F, Vn, 1024);
    k_bias_act<<<(NN1F * Bn + 255) / 256, 256>>>((float*)p_ynn1, nn1_b, (float*)p_xn1, NN1F * Bn, 1);
    cudaMemsetAsync(p_ynn2, 0, (size_t)NN2F * Bn * sizeof(float));
    k_gemm<<<dim3(NN2F / 64, 4), 256>>>((float*)p_xn1, nn2_w, (float*)p_ynn2, NN2F, NN1F, 256);
    k_bias_act<<<(NN2F * Bn + 255) / 256, 256>>>((float*)p_ynn2, nn2_b, (float*)p_xn2, NN2F * Bn, 1);

    // decode branch
    cudaMemsetAsync(p_yfc2, 0, (size_t)FC2F * Bn * sizeof(float));
    k_gemm<<<dim3(FC2F / 64, 4), 256>>>((float*)p_hid, fc2_w, (float*)p_yfc2, FC2F, FC1F, 128);
    k_bias_act<<<(FC2F * Bn + 255) / 256, 256>>>((float*)p_yfc2, fc2_b, (float*)p_xd, FC2F * Bn, 1);
    cudaMemsetAsync(p_yfc3, 0, (size_t)Vn * Bn * sizeof(float));
    k_gemm<<<dim3(Vn / 64, 2), 256>>>((float*)p_xd, fc3_w, (float*)p_yfc3, Vn, FC2F, 256);
    k_fc3_out<<<dim3(Vn / 32, Bn / 32), dim3(32, 8)>>>((float*)p_yfc3, fc3_b, out_dec);

    // classifier head
    k_sum2<<<Bn, 256>>>((float*)p_hid, (float*)p_xn2, sum2_w, sum2_b, out_lp);
}

// round 8
// speedup vs baseline: 1.5202x; 1.5202x over previous
#include <cuda_runtime.h>
#include <cuda_bf16.h>
#include <math.h>
#include <stdint.h>

#define Bn     64
#define Vn     16384
#define En     524288
#define Kc     6
#define F1     32
#define POOLn  8
#define VG     (Vn / POOLn)       // 2048
#define FC1FIN (F1 * VG)          // 65536
#define FC1F   512
#define FC2F   512
#define NN1F   1024
#define NN2F   512
#define OUTC   10

// ---------------- scratch (device globals; no runtime allocation) ----------
__device__ __align__(16) float g_xs[6 * Vn * Bn];        // Chebyshev basis, [k][v][b]
__device__ __align__(16) float g_pooled[FC1FIN * Bn];    // [i][b]
__device__ __align__(16) float g_yfc1[FC1F * Bn];
__device__ __align__(16) float g_hid[FC1F * Bn];
__device__ __align__(16) float g_yfc2[FC2F * Bn];
__device__ __align__(16) float g_xd[FC2F * Bn];
__device__ __align__(16) float g_yfc3[Vn * Bn];
__device__ __align__(16) float g_ynn1[NN1F * Bn];
__device__ __align__(16) float g_xn1[NN1F * Bn];
__device__ __align__(16) float g_ynn2[NN2F * Bn];
__device__ __align__(16) float g_xn2[NN2F * Bn];
__device__ int  g_rowptr[Vn + 1];
__device__ int  g_cursor[Vn];
__device__ __align__(8) int2 g_csr[En];                  // (col, val bits)

// ---------------- warp MMA helpers (baseline PTX, no 'a' features) ----------
__device__ __forceinline__ uint32_t smem_u32(const void* p) {
    uint32_t a;
    asm("{ .reg .u64 t; cvta.to.shared.u64 t, %1; cvt.u32.u64 %0, t; }" : "=r"(a) : "l"(p));
    return a;
}
#define LDSM_X4(r0, r1, r2, r3, a) \
    asm volatile("ldmatrix.sync.aligned.m8n8.x4.shared.b16 {%0,%1,%2,%3}, [%4];" \
                 : "=r"(r0), "=r"(r1), "=r"(r2), "=r"(r3) : "r"(a))
#define LDSM_X2T(r0, r1, a) \
    asm volatile("ldmatrix.sync.aligned.m8n8.x2.trans.shared.b16 {%0,%1}, [%2];" \
                 : "=r"(r0), "=r"(r1) : "r"(a))
#define MMA16816(d, a0, a1, a2, a3, b0, b1) \
    asm volatile("mma.sync.aligned.m16n8k16.row.col.f32.bf16.bf16.f32 " \
                 "{%0,%1,%2,%3}, {%4,%5,%6,%7}, {%8,%9}, {%0,%1,%2,%3};" \
                 : "+f"((d)[0]), "+f"((d)[1]), "+f"((d)[2]), "+f"((d)[3]) \
                 : "r"(a0), "r"(a1), "r"(a2), "r"(a3), "r"(b0), "r"(b1))

// ---------------- transpose x_in [64][V] -> [V][64] ------------------------
__global__ void k_transpose_in(const float* __restrict__ xin, float* __restrict__ xout) {
    __shared__ float t[32][33];
    int v0 = blockIdx.x * 32, b0 = blockIdx.y * 32;
    int tx = threadIdx.x, ty = threadIdx.y;
    #pragma unroll
    for (int j = 0; j < 32; j += 8)
        t[ty + j][tx] = xin[(size_t)(b0 + ty + j) * Vn + v0 + tx];
    __syncthreads();
    #pragma unroll
    for (int j = 0; j < 32; j += 8)
        xout[(size_t)(v0 + ty + j) * Bn + b0 + tx] = t[tx][ty + j];
}

// ---------------- CSR build -------------------------------------------------
__global__ void k_hist(const int* __restrict__ rows) {
    int e = blockIdx.x * 256 + threadIdx.x;
    if (e < En) atomicAdd(&g_rowptr[rows[e] + 1], 1);
}

__global__ void k_scan() {   // 1 block, 1024 threads, V = 1024*16
    __shared__ int sm[1024];
    int tid = threadIdx.x;
    int loc[16];
    int base = 1 + tid * 16;
    int s = 0;
    #pragma unroll
    for (int j = 0; j < 16; j++) { loc[j] = g_rowptr[base + j]; s += loc[j]; }
    sm[tid] = s;
    __syncthreads();
    for (int off = 1; off < 1024; off <<= 1) {
        int v = (tid >= off) ? sm[tid - off] : 0;
        __syncthreads();
        sm[tid] += v;
        __syncthreads();
    }
    int run = sm[tid] - s;   // exclusive prefix of this thread's chunk
    #pragma unroll
    for (int j = 0; j < 16; j++) { run += loc[j]; g_rowptr[base + j] = run; }
}

__global__ void k_scatter(const int* __restrict__ rows, const int* __restrict__ cols,
                          const float* __restrict__ vals) {
    int e = blockIdx.x * 256 + threadIdx.x;
    if (e < En) {
        int r = rows[e];
        int p = g_rowptr[r] + atomicAdd(&g_cursor[r], 1);
        g_csr[p] = make_int2(cols[e], __float_as_int(vals[e]));
    }
}

// ---------------- SpMM: out = alpha * (L @ x) + beta * prev ----------------
__global__ void k_spmm(const float* __restrict__ xin, const float* __restrict__ prev,
                       float* __restrict__ xout, float alpha, float beta) {
    int warp = threadIdx.x >> 5, lane = threadIdx.x & 31;
    int row = blockIdx.x * 8 + warp;
    int s = g_rowptr[row], e = g_rowptr[row + 1];
    const float2* __restrict__ xin2 = (const float2*)xin;
    float2 acc = make_float2(0.f, 0.f);
    int i = s;
    for (; i + 1 < e; i += 2) {
        int2 cv0 = g_csr[i];
        int2 cv1 = g_csr[i + 1];
        float2 x0 = xin2[(size_t)cv0.x * 32 + lane];
        float2 x1 = xin2[(size_t)cv1.x * 32 + lane];
        float v0 = __int_as_float(cv0.y), v1 = __int_as_float(cv1.y);
        acc.x += v0 * x0.x; acc.y += v0 * x0.y;
        acc.x += v1 * x1.x; acc.y += v1 * x1.y;
    }
    if (i < e) {
        int2 cv = g_csr[i];
        float2 xv = xin2[(size_t)cv.x * 32 + lane];
        float v = __int_as_float(cv.y);
        acc.x += v * xv.x; acc.y += v * xv.y;
    }
    size_t o = (size_t)row * 32 + lane;
    float2 pv = ((const float2*)prev)[o];
    float2 r;
    r.x = alpha * acc.x + beta * pv.x;
    r.y = alpha * acc.y + beta * pv.y;
    ((float2*)xout)[o] = r;
}

// ---------------- fused cheby-combine + relu + maxpool ----------------------
__global__ void k_chebypool(const float* __restrict__ w, const float* __restrict__ bias) {
    __shared__ float sw[F1 * Kc];
    __shared__ float sb[F1];
    int tid = threadIdx.y * 64 + threadIdx.x;
    if (tid < F1 * Kc) sw[tid] = w[tid];
    if (tid >= F1 * Kc && tid < F1 * Kc + F1) sb[tid - F1 * Kc] = bias[tid - F1 * Kc];
    __syncthreads();
    int b  = threadIdx.x;
    int vg = blockIdx.x * 4 + threadIdx.y;
    float mx[F1];
    #pragma unroll
    for (int f = 0; f < F1; f++) mx[f] = -INFINITY;
    int v0 = vg * POOLn;
    for (int v = v0; v < v0 + POOLn; v++) {
        float t[Kc];
        #pragma unroll
        for (int k = 0; k < Kc; k++)
            t[k] = g_xs[(size_t)k * Vn * Bn + (size_t)v * Bn + b];
        #pragma unroll
        for (int f = 0; f < F1; f++) {
            float s = sb[f];
            #pragma unroll
            for (int k = 0; k < Kc; k++) s += t[k] * sw[f * Kc + k];
            mx[f] = fmaxf(mx[f], s);
        }
    }
    #pragma unroll
    for (int f = 0; f < F1; f++)
        g_pooled[((size_t)vg * F1 + f) * Bn + b] = fmaxf(mx[f], 0.f);
}

// ---------------- split-bf16 tensor GEMM (mma.sync HMMA) --------------------
// Y[n][b] += sum_k X[k][b] * W[n][k]; CTA tile 128n x 64b; k-chunk 32.
// D += Whi*Xhi + Whi*Xlo + Wlo*Xhi  (fp32 accum; lo*lo dropped ~2^-18).
// grid (N/128, K/kspan), block 256 (8 warps, each 32n x 32b).
__global__ __launch_bounds__(256)
void k_mmagemm(const float* __restrict__ X, const float* __restrict__ W,
               float* __restrict__ Y, int K, int kspan) {
    __shared__ __align__(16) __nv_bfloat16 sWhi[128][40];   // 80B stride: ldsm conflict-free
    __shared__ __align__(16) __nv_bfloat16 sWlo[128][40];
    __shared__ __align__(16) __nv_bfloat16 sXhi[32][72];    // 144B stride: conflict-free
    __shared__ __align__(16) __nv_bfloat16 sXlo[32][72];
    int tid = threadIdx.x, lane = tid & 31, wid = tid >> 5;
    int n0 = blockIdx.x * 128;
    int k0 = blockIdx.y * kspan;
    int nw = (wid >> 1) * 32;     // warp n-offset within tile
    int bw = (wid & 1) * 32;      // warp b-offset
    float acc[2][4][4] = {};
    for (int kc = k0; kc < k0 + kspan; kc += 32) {
        __syncthreads();
        // W chunk: 128 rows x 32 k (2048 float2, 8/thread)
        #pragma unroll
        for (int i = 0; i < 8; i++) {
            int idx = tid + i * 256;
            int r = idx >> 4, j = (idx & 15) * 2;
            float2 v = *(const float2*)(W + (size_t)(n0 + r) * K + kc + j);
            __nv_bfloat16 h0 = __float2bfloat16(v.x);
            __nv_bfloat16 h1 = __float2bfloat16(v.y);
            sWhi[r][j] = h0; sWhi[r][j + 1] = h1;
            sWlo[r][j]     = __float2bfloat16(v.x - __bfloat162float(h0));
            sWlo[r][j + 1] = __float2bfloat16(v.y - __bfloat162float(h1));
        }
        // X chunk: 32 k x 64 b (1024 float2, 4/thread)
        #pragma unroll
        for (int i = 0; i < 4; i++) {
            int idx = tid + i * 256;
            int k = idx >> 5, b = (idx & 31) * 2;
            float2 v = *(const float2*)(X + (size_t)(kc + k) * 64 + b);
            __nv_bfloat16 h0 = __float2bfloat16(v.x);
            __nv_bfloat16 h1 = __float2bfloat16(v.y);
            sXhi[k][b] = h0; sXhi[k][b + 1] = h1;
            sXlo[k][b]     = __float2bfloat16(v.x - __bfloat162float(h0));
            sXlo[k][b + 1] = __float2bfloat16(v.y - __bfloat162float(h1));
        }
        __syncthreads();
        #pragma unroll
        for (int s = 0; s < 2; s++) {      // two k16 steps
            int ar = nw + (lane & 15);
            int ac = s * 16 + (lane >> 4) * 8;
            uint32_t ahi[2][4], alo[2][4];
            #pragma unroll
            for (int mt = 0; mt < 2; mt++) {
                LDSM_X4(ahi[mt][0], ahi[mt][1], ahi[mt][2], ahi[mt][3],
                        smem_u32(&sWhi[ar + mt * 16][ac]));
                LDSM_X4(alo[mt][0], alo[mt][1], alo[mt][2], alo[mt][3],
                        smem_u32(&sWlo[ar + mt * 16][ac]));
            }
            int br = s * 16 + (lane & 15);
            #pragma unroll
            for (int nt = 0; nt < 4; nt++) {
                uint32_t bh0, bh1, bl0, bl1;
                LDSM_X2T(bh0, bh1, smem_u32(&sXhi[br][bw + nt * 8]));
                LDSM_X2T(bl0, bl1, smem_u32(&sXlo[br][bw + nt * 8]));
                #pragma unroll
                for (int mt = 0; mt < 2; mt++) {
                    MMA16816(acc[mt][nt], ahi[mt][0], ahi[mt][1], ahi[mt][2], ahi[mt][3], bh0, bh1);
                    MMA16816(acc[mt][nt], ahi[mt][0], ahi[mt][1], ahi[mt][2], ahi[mt][3], bl0, bl1);
                    MMA16816(acc[mt][nt], alo[mt][0], alo[mt][1], alo[mt][2], alo[mt][3], bh0, bh1);
                }
            }
        }
    }
    // epilogue: d-frag mapping -> atomicAdd (split-K)
    #pragma unroll
    for (int mt = 0; mt < 2; mt++) {
        int n = n0 + nw + mt * 16 + (lane >> 2);
        #pragma unroll
        for (int nt = 0; nt < 4; nt++) {
            int b = bw + nt * 8 + (lane & 3) * 2;
            atomicAdd(&Y[(size_t)n * 64 + b],           acc[mt][nt][0]);
            atomicAdd(&Y[(size_t)n * 64 + b + 1],       acc[mt][nt][1]);
            atomicAdd(&Y[(size_t)(n + 8) * 64 + b],     acc[mt][nt][2]);
            atomicAdd(&Y[(size_t)(n + 8) * 64 + b + 1], acc[mt][nt][3]);
        }
    }
}

// ---------------- scalar fp32 GEMM (small fc2/nn2) ---------------------------
__global__ __launch_bounds__(256)
void k_gemm(const float* __restrict__ X, const float* __restrict__ W,
            float* __restrict__ Y, int N, int K, int kspan) {
    const int KC = 32;
    __shared__ __align__(16) float Xs[KC * 64];
    __shared__ __align__(16) float Ws[KC][68];
    int tid = threadIdx.x;
    int n0 = blockIdx.x * 64;
    int k0 = blockIdx.y * kspan;
    int k1 = min(K, k0 + kspan);
    int bg = tid & 15;
    int ng = tid >> 4;
    float a00=0,a01=0,a02=0,a03=0, a10=0,a11=0,a12=0,a13=0;
    float a20=0,a21=0,a22=0,a23=0, a30=0,a31=0,a32=0,a33=0;
    int wrow = tid >> 2;
    int wj0  = (tid & 3) * 4;
    for (int kb = k0; kb < k1; kb += KC) {
        __syncthreads();
        {
            const float4* Xg = (const float4*)(X + (size_t)kb * 64);
            float4* Xs4 = (float4*)Xs;
            Xs4[tid]       = Xg[tid];
            Xs4[tid + 256] = Xg[tid + 256];
        }
        {
            #pragma unroll
            for (int h = 0; h < 2; h++) {
                int jj = wj0 + h * 16;
                float4 wv = *(const float4*)(W + (size_t)(n0 + wrow) * K + kb + jj);
                Ws[jj + 0][wrow] = wv.x;
                Ws[jj + 1][wrow] = wv.y;
                Ws[jj + 2][wrow] = wv.z;
                Ws[jj + 3][wrow] = wv.w;
            }
        }
        __syncthreads();
        #pragma unroll
        for (int k = 0; k < KC; k++) {
            float4 xv = *(const float4*)(Xs + k * 64 + bg * 4);
            float4 wv = *(const float4*)(&Ws[k][ng * 4]);
            a00 += wv.x * xv.x; a01 += wv.x * xv.y; a02 += wv.x * xv.z; a03 += wv.x * xv.w;
            a10 += wv.y * xv.x; a11 += wv.y * xv.y; a12 += wv.y * xv.z; a13 += wv.y * xv.w;
            a20 += wv.z * xv.x; a21 += wv.z * xv.y; a22 += wv.z * xv.z; a23 += wv.z * xv.w;
            a30 += wv.w * xv.x; a31 += wv.w * xv.y; a32 += wv.w * xv.z; a33 += wv.w * xv.w;
        }
    }
    float* y = Y + (size_t)(n0 + ng * 4) * 64 + bg * 4;
    atomicAdd(y + 0*64 + 0, a00); atomicAdd(y + 0*64 + 1, a01); atomicAdd(y + 0*64 + 2, a02); atomicAdd(y + 0*64 + 3, a03);
    atomicAdd(y + 1*64 + 0, a10); atomicAdd(y + 1*64 + 1, a11); atomicAdd(y + 1*64 + 2, a12); atomicAdd(y + 1*64 + 3, a13);
    atomicAdd(y + 2*64 + 0, a20); atomicAdd(y + 2*64 + 1, a21); atomicAdd(y + 2*64 + 2, a22); atomicAdd(y + 2*64 + 3, a23);
    atomicAdd(y + 3*64 + 0, a30); atomicAdd(y + 3*64 + 1, a31); atomicAdd(y + 3*64 + 2, a32); atomicAdd(y + 3*64 + 3, a33);
}

// ---------------- epilogues -------------------------------------------------
__global__ void k_bias_act(const float* __restrict__ Y, const float* __restrict__ bias,
                           float* __restrict__ dst, int total, int relu) {
    int i = blockIdx.x * 256 + threadIdx.x;
    if (i < total) {
        int n = i >> 6;
        float v = Y[i] + bias[n];
        if (relu) v = fmaxf(v, 0.f);
        dst[i] = v;
    }
}

__global__ void k_copy_hidden(const float* __restrict__ hid, float* __restrict__ out2) {
    int i = blockIdx.x * 256 + threadIdx.x;
    if (i < FC1F * Bn) {
        int n = i >> 6, b = i & 63;
        out2[b * FC1F + n] = hid[i];
    }
}

__global__ void k_fc3_out(const float* __restrict__ Y, const float* __restrict__ bias,
                          float* __restrict__ out) {
    __shared__ float t[32][33];
    int v0 = blockIdx.x * 32, b0 = blockIdx.y * 32;
    int tx = threadIdx.x, ty = threadIdx.y;
    #pragma unroll
    for (int j = 0; j < 32; j += 8)
        t[ty + j][tx] = Y[(size_t)(v0 + ty + j) * 64 + b0 + tx] + bias[v0 + ty + j];
    __syncthreads();
    #pragma unroll
    for (int j = 0; j < 32; j += 8)
        out[(size_t)(b0 + ty + j) * Vn + v0 + tx] = t[tx][ty + j];
}

// ---------------- fused sum2 + log_softmax ----------------------------------
__global__ void k_sum2(const float* __restrict__ hid, const float* __restrict__ xn2,
                       const float* __restrict__ w, const float* __restrict__ bias,
                       float* __restrict__ outlp) {
    int b = blockIdx.x, tid = threadIdx.x;
    float acc[OUTC];
    #pragma unroll
    for (int n = 0; n < OUTC; n++) acc[n] = 0.f;
    for (int k = tid; k < FC1F + NN2F; k += 256) {
        float xv = (k < FC1F) ? hid[k * 64 + b] : xn2[(k - FC1F) * 64 + b];
        #pragma unroll
        for (int n = 0; n < OUTC; n++) acc[n] += xv * w[n * (FC1F + NN2F) + k];
    }
    #pragma unroll
    for (int off = 16; off; off >>= 1)
        #pragma unroll
        for (int n = 0; n < OUTC; n++)
            acc[n] += __shfl_down_sync(0xffffffffu, acc[n], off);
    __shared__ float red[8][OUTC];
    int lane = tid & 31, wp = tid >> 5;
    if (lane == 0)
        #pragma unroll
        for (int n = 0; n < OUTC; n++) red[wp][n] = acc[n];
    __syncthreads();
    if (tid == 0) {
        float z[OUTC];
        #pragma unroll
        for (int n = 0; n < OUTC; n++) {
            float s = bias[n];
            #pragma unroll
            for (int w8 = 0; w8 < 8; w8++) s += red[w8][n];
            z[n] = s;
        }
        float m = z[0];
        #pragma unroll
        for (int n = 1; n < OUTC; n++) m = fmaxf(m, z[n]);
        float se = 0.f;
        #pragma unroll
        for (int n = 0; n < OUTC; n++) se += expf(z[n] - m);
        float l = m + logf(se);
        #pragma unroll
        for (int n = 0; n < OUTC; n++) outlp[b * OUTC + n] = z[n] - l;
    }
}

// ---------------- launcher --------------------------------------------------
extern "C" void kernel_launch(void* const* d_in, const int* in_sizes, int n_in,
                              void* d_out, int out_size) {
    const float* x_in   = (const float*)d_in[0];
    const float* L_vals = (const float*)d_in[1];
    const float* cl1_w  = (const float*)d_in[2];
    const float* cl1_b  = (const float*)d_in[3];
    const float* fc1_w  = (const float*)d_in[4];
    const float* fc1_b  = (const float*)d_in[5];
    const float* fc2_w  = (const float*)d_in[6];
    const float* fc2_b  = (const float*)d_in[7];
    const float* fc3_w  = (const float*)d_in[8];
    const float* fc3_b  = (const float*)d_in[9];
    const float* nn1_w  = (const float*)d_in[10];
    const float* nn1_b  = (const float*)d_in[11];
    const float* nn2_w  = (const float*)d_in[12];
    const float* nn2_b  = (const float*)d_in[13];
    const float* sum2_w = (const float*)d_in[14];
    const float* sum2_b = (const float*)d_in[15];
    const int*   L_rows = (const int*)d_in[16];
    const int*   L_cols = (const int*)d_in[17];

    float* out = (float*)d_out;
    float* out_dec = out;                       // [64][16384]
    float* out_hid = out + (size_t)Bn * Vn;     // [64][512]
    float* out_lp  = out_hid + Bn * FC1F;       // [64][10]

    void *p_xs, *p_pooled, *p_yfc1, *p_hid, *p_yfc2, *p_xd, *p_yfc3;
    void *p_ynn1, *p_xn1, *p_ynn2, *p_xn2, *p_rowptr, *p_cursor;
    cudaGetSymbolAddress(&p_xs, g_xs);
    cudaGetSymbolAddress(&p_pooled, g_pooled);
    cudaGetSymbolAddress(&p_yfc1, g_yfc1);
    cudaGetSymbolAddress(&p_hid, g_hid);
    cudaGetSymbolAddress(&p_yfc2, g_yfc2);
    cudaGetSymbolAddress(&p_xd, g_xd);
    cudaGetSymbolAddress(&p_yfc3, g_yfc3);
    cudaGetSymbolAddress(&p_ynn1, g_ynn1);
    cudaGetSymbolAddress(&p_xn1, g_xn1);
    cudaGetSymbolAddress(&p_ynn2, g_ynn2);
    cudaGetSymbolAddress(&p_xn2, g_xn2);
    cudaGetSymbolAddress(&p_rowptr, g_rowptr);
    cudaGetSymbolAddress(&p_cursor, g_cursor);

    float* xs     = (float*)p_xs;
    float* pooled = (float*)p_pooled;
    const size_t VB = (size_t)Vn * Bn;

    // CSR build + input transpose
    cudaMemsetAsync(p_rowptr, 0, (Vn + 1) * sizeof(int));
    cudaMemsetAsync(p_cursor, 0, Vn * sizeof(int));
    k_transpose_in<<<dim3(Vn / 32, Bn / 32), dim3(32, 8)>>>(x_in, xs);
    k_hist<<<En / 256, 256>>>(L_rows);
    k_scan<<<1, 1024>>>();
    k_scatter<<<En / 256, 256>>>(L_rows, L_cols, L_vals);

    // Chebyshev recursion: xs[k] = 2 L xs[k-1] - xs[k-2]
    k_spmm<<<Vn / 8, 256>>>(xs,          xs,          xs + VB,     1.f,  0.f);
    k_spmm<<<Vn / 8, 256>>>(xs + VB,     xs,          xs + 2 * VB, 2.f, -1.f);
    k_spmm<<<Vn / 8, 256>>>(xs + 2 * VB, xs + VB,     xs + 3 * VB, 2.f, -1.f);
    k_spmm<<<Vn / 8, 256>>>(xs + 3 * VB, xs + 2 * VB, xs + 4 * VB, 2.f, -1.f);
    k_spmm<<<Vn / 8, 256>>>(xs + 4 * VB, xs + 3 * VB, xs + 5 * VB, 2.f, -1.f);

    // combine + relu + maxpool -> pooled [65536][64]
    k_chebypool<<<VG / 4, dim3(64, 4)>>>(cl1_w, cl1_b);

    // fc1 -> hidden (HMMA split-bf16, split-K 32)
    cudaMemsetAsync(p_yfc1, 0, (size_t)FC1F * Bn * sizeof(float));
    k_mmagemm<<<dim3(FC1F / 128, 32), 256>>>(pooled, fc1_w, (float*)p_yfc1, FC1FIN, 2048);
    k_bias_act<<<(FC1F * Bn + 255) / 256, 256>>>((float*)p_yfc1, fc1_b, (float*)p_hid, FC1F * Bn, 1);
    k_copy_hidden<<<(FC1F * Bn + 255) / 256, 256>>>((float*)p_hid, out_hid);

    // nn branch (input = x_in^T = xs[0])
    cudaMemsetAsync(p_ynn1, 0, (size_t)NN1F * Bn * sizeof(float));
    k_mmagemm<<<dim3(NN1F / 128, 16), 256>>>(xs, nn1_w, (float*)p_ynn1, Vn, 1024);
    k_bias_act<<<(NN1F * Bn + 255) / 256, 256>>>((float*)p_ynn1, nn1_b, (float*)p_xn1, NN1F * Bn, 1);
    cudaMemsetAsync(p_ynn2, 0, (size_t)NN2F * Bn * sizeof(float));
    k_gemm<<<dim3(NN2F / 64, 4), 256>>>((float*)p_xn1, nn2_w, (float*)p_ynn2, NN2F, NN1F, 256);
    k_bias_act<<<(NN2F * Bn + 255) / 256, 256>>>((float*)p_ynn2, nn2_b, (float*)p_xn2, NN2F * Bn, 1);

    // decode branch
    cudaMemsetAsync(p_yfc2, 0, (size_t)FC2F * Bn * sizeof(float));
    k_gemm<<<dim3(FC2F / 64, 4), 256>>>((float*)p_hid, fc2_w, (float*)p_yfc2, FC2F, FC1F, 128);
    k_bias_act<<<(FC2F * Bn + 255) / 256, 256>>>((float*)p_yfc2, fc2_b, (float*)p_xd, FC2F * Bn, 1);
    cudaMemsetAsync(p_yfc3, 0, (size_t)Vn * Bn * sizeof(float));
    k_mmagemm<<<dim3(Vn / 128, 1), 256>>>((float*)p_xd, fc3_w, (float*)p_yfc3, FC2F, 512);
    k_fc3_out<<<dim3(Vn / 32, Bn / 32), dim3(32, 8)>>>((float*)p_yfc3, fc3_b, out_dec);

    // classifier head
    k_sum2<<<Bn, 256>>>((float*)p_hid, (float*)p_xn2, sum2_w, sum2_b, out_lp);
}

// round 9
// speedup vs baseline: 1.8523x; 1.2185x over previous
#include <cuda_runtime.h>
#include <cuda_bf16.h>
#include <math.h>
#include <stdint.h>

#define Bn     64
#define Vn     16384
#define En     524288
#define Kc     6
#define F1     32
#define POOLn  8
#define VG     (Vn / POOLn)       // 2048
#define FC1FIN (F1 * VG)          // 65536
#define FC1F   512
#define FC2F   512
#define NN1F   1024
#define NN2F   512
#define OUTC   10

// ---------------- scratch (device globals; no runtime allocation) ----------
__device__ __align__(16) float g_xs[6 * Vn * Bn];        // Chebyshev basis, [k][v][b]
__device__ __align__(16) float g_pooled[FC1FIN * Bn];    // [i][b]
// one contiguous union of all GEMM outputs -> single memset node
// layout: yfc1 | ynn1 | ynn2 | yfc2 | yfc3
#define YU_FC1  0
#define YU_NN1  (FC1F * Bn)
#define YU_NN2  (YU_NN1 + NN1F * Bn)
#define YU_FC2  (YU_NN2 + NN2F * Bn)
#define YU_FC3  (YU_FC2 + FC2F * Bn)
#define YU_TOT  (YU_FC3 + Vn * Bn)
__device__ __align__(16) float g_yuni[YU_TOT];
__device__ __align__(16) float g_hid[FC1F * Bn];
__device__ __align__(16) float g_xd[FC2F * Bn];
__device__ __align__(16) float g_xn1[NN1F * Bn];
__device__ __align__(16) float g_xn2[NN2F * Bn];
__device__ int  g_rowptr[Vn + 1];
__device__ int  g_cursor[Vn];
__device__ __align__(8) int2 g_csr[En];                  // (col, val bits)

// ---------------- warp MMA helpers (baseline PTX, no 'a' features) ----------
__device__ __forceinline__ uint32_t smem_u32(const void* p) {
    uint32_t a;
    asm("{ .reg .u64 t; cvta.to.shared.u64 t, %1; cvt.u32.u64 %0, t; }" : "=r"(a) : "l"(p));
    return a;
}
#define LDSM_X4(r0, r1, r2, r3, a) \
    asm volatile("ldmatrix.sync.aligned.m8n8.x4.shared.b16 {%0,%1,%2,%3}, [%4];" \
                 : "=r"(r0), "=r"(r1), "=r"(r2), "=r"(r3) : "r"(a))
#define LDSM_X2T(r0, r1, a) \
    asm volatile("ldmatrix.sync.aligned.m8n8.x2.trans.shared.b16 {%0,%1}, [%2];" \
                 : "=r"(r0), "=r"(r1) : "r"(a))
#define MMA16816(d, a0, a1, a2, a3, b0, b1) \
    asm volatile("mma.sync.aligned.m16n8k16.row.col.f32.bf16.bf16.f32 " \
                 "{%0,%1,%2,%3}, {%4,%5,%6,%7}, {%8,%9}, {%0,%1,%2,%3};" \
                 : "+f"((d)[0]), "+f"((d)[1]), "+f"((d)[2]), "+f"((d)[3]) \
                 : "r"(a0), "r"(a1), "r"(a2), "r"(a3), "r"(b0), "r"(b1))

// ---------------- transpose x_in [64][V] -> [V][64] ------------------------
__global__ void k_transpose_in(const float* __restrict__ xin, float* __restrict__ xout) {
    __shared__ float t[32][33];
    int v0 = blockIdx.x * 32, b0 = blockIdx.y * 32;
    int tx = threadIdx.x, ty = threadIdx.y;
    #pragma unroll
    for (int j = 0; j < 32; j += 8)
        t[ty + j][tx] = xin[(size_t)(b0 + ty + j) * Vn + v0 + tx];
    __syncthreads();
    #pragma unroll
    for (int j = 0; j < 32; j += 8)
        xout[(size_t)(v0 + ty + j) * Bn + b0 + tx] = t[tx][ty + j];
}

// ---------------- CSR build -------------------------------------------------
__global__ void k_hist(const int* __restrict__ rows) {
    int e = blockIdx.x * 256 + threadIdx.x;
    if (e < En) atomicAdd(&g_rowptr[rows[e] + 1], 1);
}

__global__ void k_scan() {   // 1 block, 1024 threads; also zeroes g_cursor
    __shared__ int sm[1024];
    int tid = threadIdx.x;
    int loc[16];
    int base = 1 + tid * 16;
    int s = 0;
    #pragma unroll
    for (int j = 0; j < 16; j++) { loc[j] = g_rowptr[base + j]; s += loc[j]; }
    sm[tid] = s;
    __syncthreads();
    for (int off = 1; off < 1024; off <<= 1) {
        int v = (tid >= off) ? sm[tid - off] : 0;
        __syncthreads();
        sm[tid] += v;
        __syncthreads();
    }
    int run = sm[tid] - s;   // exclusive prefix of this thread's chunk
    #pragma unroll
    for (int j = 0; j < 16; j++) {
        run += loc[j];
        g_rowptr[base + j] = run;
        g_cursor[tid * 16 + j] = 0;
    }
}

__global__ void k_scatter(const int* __restrict__ rows, const int* __restrict__ cols,
                          const float* __restrict__ vals) {
    int e = blockIdx.x * 256 + threadIdx.x;
    if (e < En) {
        int r = rows[e];
        int p = g_rowptr[r] + atomicAdd(&g_cursor[r], 1);
        g_csr[p] = make_int2(cols[e], __float_as_int(vals[e]));
    }
}

// ---------------- SpMM: out = alpha * (L @ x) + beta * prev ----------------
__global__ void k_spmm(const float* __restrict__ xin, const float* __restrict__ prev,
                       float* __restrict__ xout, float alpha, float beta) {
    int warp = threadIdx.x >> 5, lane = threadIdx.x & 31;
    int row = blockIdx.x * 8 + warp;
    int s = g_rowptr[row], e = g_rowptr[row + 1];
    const float2* __restrict__ xin2 = (const float2*)xin;
    float2 acc = make_float2(0.f, 0.f);
    int i = s;
    for (; i + 1 < e; i += 2) {
        int2 cv0 = g_csr[i];
        int2 cv1 = g_csr[i + 1];
        float2 x0 = xin2[(size_t)cv0.x * 32 + lane];
        float2 x1 = xin2[(size_t)cv1.x * 32 + lane];
        float v0 = __int_as_float(cv0.y), v1 = __int_as_float(cv1.y);
        acc.x += v0 * x0.x; acc.y += v0 * x0.y;
        acc.x += v1 * x1.x; acc.y += v1 * x1.y;
    }
    if (i < e) {
        int2 cv = g_csr[i];
        float2 xv = xin2[(size_t)cv.x * 32 + lane];
        float v = __int_as_float(cv.y);
        acc.x += v * xv.x; acc.y += v * xv.y;
    }
    size_t o = (size_t)row * 32 + lane;
    float2 pv = ((const float2*)prev)[o];
    float2 r;
    r.x = alpha * acc.x + beta * pv.x;
    r.y = alpha * acc.y + beta * pv.y;
    ((float2*)xout)[o] = r;
}

// ---------------- fused cheby-combine + relu + maxpool ----------------------
__global__ void k_chebypool(const float* __restrict__ w, const float* __restrict__ bias) {
    __shared__ float sw[F1 * Kc];
    __shared__ float sb[F1];
    int tid = threadIdx.y * 64 + threadIdx.x;
    if (tid < F1 * Kc) sw[tid] = w[tid];
    if (tid >= F1 * Kc && tid < F1 * Kc + F1) sb[tid - F1 * Kc] = bias[tid - F1 * Kc];
    __syncthreads();
    int b  = threadIdx.x;
    int vg = blockIdx.x * 4 + threadIdx.y;
    float mx[F1];
    #pragma unroll
    for (int f = 0; f < F1; f++) mx[f] = -INFINITY;
    int v0 = vg * POOLn;
    for (int v = v0; v < v0 + POOLn; v++) {
        float t[Kc];
        #pragma unroll
        for (int k = 0; k < Kc; k++)
            t[k] = g_xs[(size_t)k * Vn * Bn + (size_t)v * Bn + b];
        #pragma unroll
        for (int f = 0; f < F1; f++) {
            float s = sb[f];
            #pragma unroll
            for (int k = 0; k < Kc; k++) s += t[k] * sw[f * Kc + k];
            mx[f] = fmaxf(mx[f], s);
        }
    }
    #pragma unroll
    for (int f = 0; f < F1; f++)
        g_pooled[((size_t)vg * F1 + f) * Bn + b] = fmaxf(mx[f], 0.f);
}

// ---------------- split-bf16 tensor GEMM (mma.sync HMMA) --------------------
// Y[n][b] += sum_k X[k][b] * W[n][k]; CTA tile 128n x 64b; k-chunk 32.
// D += Whi*Xhi + Whi*Xlo + Wlo*Xhi  (fp32 accum; lo*lo dropped ~2^-18).
// grid (N/128, K/kspan), block 256 (8 warps, each 32n x 32b), 2 CTAs/SM.
// Term-major MMA order: 8 distinct accumulators between reuses -> no RAW stall.
__global__ __launch_bounds__(256, 2)
void k_mmagemm(const float* __restrict__ X, const float* __restrict__ W,
               float* __restrict__ Y, int K, int kspan) {
    __shared__ __align__(16) __nv_bfloat16 sWhi[128][40];   // 80B stride: ldsm conflict-free
    __shared__ __align__(16) __nv_bfloat16 sWlo[128][40];
    __shared__ __align__(16) __nv_bfloat16 sXhi[32][72];    // 144B stride: conflict-free
    __shared__ __align__(16) __nv_bfloat16 sXlo[32][72];
    int tid = threadIdx.x, lane = tid & 31, wid = tid >> 5;
    int n0 = blockIdx.x * 128;
    int k0 = blockIdx.y * kspan;
    int nw = (wid >> 1) * 32;     // warp n-offset within tile
    int bw = (wid & 1) * 32;      // warp b-offset
    float acc[2][4][4] = {};
    for (int kc = k0; kc < k0 + kspan; kc += 32) {
        __syncthreads();
        // W chunk: 128 rows x 32 k (2048 float2, 8/thread)
        #pragma unroll
        for (int i = 0; i < 8; i++) {
            int idx = tid + i * 256;
            int r = idx >> 4, j = (idx & 15) * 2;
            float2 v = *(const float2*)(W + (size_t)(n0 + r) * K + kc + j);
            __nv_bfloat16 h0 = __float2bfloat16(v.x);
            __nv_bfloat16 h1 = __float2bfloat16(v.y);
            sWhi[r][j] = h0; sWhi[r][j + 1] = h1;
            sWlo[r][j]     = __float2bfloat16(v.x - __bfloat162float(h0));
            sWlo[r][j + 1] = __float2bfloat16(v.y - __bfloat162float(h1));
        }
        // X chunk: 32 k x 64 b (1024 float2, 4/thread)
        #pragma unroll
        for (int i = 0; i < 4; i++) {
            int idx = tid + i * 256;
            int k = idx >> 5, b = (idx & 31) * 2;
            float2 v = *(const float2*)(X + (size_t)(kc + k) * 64 + b);
            __nv_bfloat16 h0 = __float2bfloat16(v.x);
            __nv_bfloat16 h1 = __float2bfloat16(v.y);
            sXhi[k][b] = h0; sXhi[k][b + 1] = h1;
            sXlo[k][b]     = __float2bfloat16(v.x - __bfloat162float(h0));
            sXlo[k][b + 1] = __float2bfloat16(v.y - __bfloat162float(h1));
        }
        __syncthreads();
        #pragma unroll
        for (int s = 0; s < 2; s++) {      // two k16 steps
            int ar = nw + (lane & 15);
            int ac = s * 16 + (lane >> 4) * 8;
            uint32_t ahi[2][4], alo[2][4];
            #pragma unroll
            for (int mt = 0; mt < 2; mt++) {
                LDSM_X4(ahi[mt][0], ahi[mt][1], ahi[mt][2], ahi[mt][3],
                        smem_u32(&sWhi[ar + mt * 16][ac]));
                LDSM_X4(alo[mt][0], alo[mt][1], alo[mt][2], alo[mt][3],
                        smem_u32(&sWlo[ar + mt * 16][ac]));
            }
            int br = s * 16 + (lane & 15);
            uint32_t bh[4][2], bl[4][2];
            #pragma unroll
            for (int nt = 0; nt < 4; nt++) {
                LDSM_X2T(bh[nt][0], bh[nt][1], smem_u32(&sXhi[br][bw + nt * 8]));
                LDSM_X2T(bl[nt][0], bl[nt][1], smem_u32(&sXlo[br][bw + nt * 8]));
            }
            // term hi*hi
            #pragma unroll
            for (int nt = 0; nt < 4; nt++)
                #pragma unroll
                for (int mt = 0; mt < 2; mt++)
                    MMA16816(acc[mt][nt], ahi[mt][0], ahi[mt][1], ahi[mt][2], ahi[mt][3],
                             bh[nt][0], bh[nt][1]);
            // term hi*lo
            #pragma unroll
            for (int nt = 0; nt < 4; nt++)
                #pragma unroll
                for (int mt = 0; mt < 2; mt++)
                    MMA16816(acc[mt][nt], ahi[mt][0], ahi[mt][1], ahi[mt][2], ahi[mt][3],
                             bl[nt][0], bl[nt][1]);
            // term lo*hi
            #pragma unroll
            for (int nt = 0; nt < 4; nt++)
                #pragma unroll
                for (int mt = 0; mt < 2; mt++)
                    MMA16816(acc[mt][nt], alo[mt][0], alo[mt][1], alo[mt][2], alo[mt][3],
                             bh[nt][0], bh[nt][1]);
        }
    }
    // epilogue: d-frag mapping -> atomicAdd (split-K)
    #pragma unroll
    for (int mt = 0; mt < 2; mt++) {
        int n = n0 + nw + mt * 16 + (lane >> 2);
        #pragma unroll
        for (int nt = 0; nt < 4; nt++) {
            int b = bw + nt * 8 + (lane & 3) * 2;
            atomicAdd(&Y[(size_t)n * 64 + b],           acc[mt][nt][0]);
            atomicAdd(&Y[(size_t)n * 64 + b + 1],       acc[mt][nt][1]);
            atomicAdd(&Y[(size_t)(n + 8) * 64 + b],     acc[mt][nt][2]);
            atomicAdd(&Y[(size_t)(n + 8) * 64 + b + 1], acc[mt][nt][3]);
        }
    }
}

// ---------------- scalar fp32 GEMM (small fc2/nn2) ---------------------------
__global__ __launch_bounds__(256)
void k_gemm(const float* __restrict__ X, const float* __restrict__ W,
            float* __restrict__ Y, int N, int K, int kspan) {
    const int KC = 32;
    __shared__ __align__(16) float Xs[KC * 64];
    __shared__ __align__(16) float Ws[KC][68];
    int tid = threadIdx.x;
    int n0 = blockIdx.x * 64;
    int k0 = blockIdx.y * kspan;
    int k1 = min(K, k0 + kspan);
    int bg = tid & 15;
    int ng = tid >> 4;
    float a00=0,a01=0,a02=0,a03=0, a10=0,a11=0,a12=0,a13=0;
    float a20=0,a21=0,a22=0,a23=0, a30=0,a31=0,a32=0,a33=0;
    int wrow = tid >> 2;
    int wj0  = (tid & 3) * 4;
    for (int kb = k0; kb < k1; kb += KC) {
        __syncthreads();
        {
            const float4* Xg = (const float4*)(X + (size_t)kb * 64);
            float4* Xs4 = (float4*)Xs;
            Xs4[tid]       = Xg[tid];
            Xs4[tid + 256] = Xg[tid + 256];
        }
        {
            #pragma unroll
            for (int h = 0; h < 2; h++) {
                int jj = wj0 + h * 16;
                float4 wv = *(const float4*)(W + (size_t)(n0 + wrow) * K + kb + jj);
                Ws[jj + 0][wrow] = wv.x;
                Ws[jj + 1][wrow] = wv.y;
                Ws[jj + 2][wrow] = wv.z;
                Ws[jj + 3][wrow] = wv.w;
            }
        }
        __syncthreads();
        #pragma unroll
        for (int k = 0; k < KC; k++) {
            float4 xv = *(const float4*)(Xs + k * 64 + bg * 4);
            float4 wv = *(const float4*)(&Ws[k][ng * 4]);
            a00 += wv.x * xv.x; a01 += wv.x * xv.y; a02 += wv.x * xv.z; a03 += wv.x * xv.w;
            a10 += wv.y * xv.x; a11 += wv.y * xv.y; a12 += wv.y * xv.z; a13 += wv.y * xv.w;
            a20 += wv.z * xv.x; a21 += wv.z * xv.y; a22 += wv.z * xv.z; a23 += wv.z * xv.w;
            a30 += wv.w * xv.x; a31 += wv.w * xv.y; a32 += wv.w * xv.z; a33 += wv.w * xv.w;
        }
    }
    float* y = Y + (size_t)(n0 + ng * 4) * 64 + bg * 4;
    atomicAdd(y + 0*64 + 0, a00); atomicAdd(y + 0*64 + 1, a01); atomicAdd(y + 0*64 + 2, a02); atomicAdd(y + 0*64 + 3, a03);
    atomicAdd(y + 1*64 + 0, a10); atomicAdd(y + 1*64 + 1, a11); atomicAdd(y + 1*64 + 2, a12); atomicAdd(y + 1*64 + 3, a13);
    atomicAdd(y + 2*64 + 0, a20); atomicAdd(y + 2*64 + 1, a21); atomicAdd(y + 2*64 + 2, a22); atomicAdd(y + 2*64 + 3, a23);
    atomicAdd(y + 3*64 + 0, a30); atomicAdd(y + 3*64 + 1, a31); atomicAdd(y + 3*64 + 2, a32); atomicAdd(y + 3*64 + 3, a33);
}

// ---------------- epilogues -------------------------------------------------
__global__ void k_bias_act(const float* __restrict__ Y, const float* __restrict__ bias,
                           float* __restrict__ dst, int total, int relu) {
    int i = blockIdx.x * 256 + threadIdx.x;
    if (i < total) {
        int n = i >> 6;
        float v = Y[i] + bias[n];
        if (relu) v = fmaxf(v, 0.f);
        dst[i] = v;
    }
}

// fc1 epilogue: bias+relu -> hid [n][b] AND out_hid [b][n] in one pass
__global__ void k_bias_act_fc1(const float* __restrict__ Y, const float* __restrict__ bias,
                               float* __restrict__ hid, float* __restrict__ out2) {
    int i = blockIdx.x * 256 + threadIdx.x;   // FC1F*Bn
    int n = i >> 6, b = i & 63;
    float v = fmaxf(Y[i] + bias[n], 0.f);
    hid[i] = v;
    out2[b * FC1F + n] = v;
}

__global__ void k_fc3_out(const float* __restrict__ Y, const float* __restrict__ bias,
                          float* __restrict__ out) {
    __shared__ float t[32][33];
    int v0 = blockIdx.x * 32, b0 = blockIdx.y * 32;
    int tx = threadIdx.x, ty = threadIdx.y;
    #pragma unroll
    for (int j = 0; j < 32; j += 8)
        t[ty + j][tx] = Y[(size_t)(v0 + ty + j) * 64 + b0 + tx] + bias[v0 + ty + j];
    __syncthreads();
    #pragma unroll
    for (int j = 0; j < 32; j += 8)
        out[(size_t)(b0 + ty + j) * Vn + v0 + tx] = t[tx][ty + j];
}

// ---------------- fused sum2 + log_softmax ----------------------------------
__global__ void k_sum2(const float* __restrict__ hid, const float* __restrict__ xn2,
                       const float* __restrict__ w, const float* __restrict__ bias,
                       float* __restrict__ outlp) {
    int b = blockIdx.x, tid = threadIdx.x;
    float acc[OUTC];
    #pragma unroll
    for (int n = 0; n < OUTC; n++) acc[n] = 0.f;
    for (int k = tid; k < FC1F + NN2F; k += 256) {
        float xv = (k < FC1F) ? hid[k * 64 + b] : xn2[(k - FC1F) * 64 + b];
        #pragma unroll
        for (int n = 0; n < OUTC; n++) acc[n] += xv * w[n * (FC1F + NN2F) + k];
    }
    #pragma unroll
    for (int off = 16; off; off >>= 1)
        #pragma unroll
        for (int n = 0; n < OUTC; n++)
            acc[n] += __shfl_down_sync(0xffffffffu, acc[n], off);
    __shared__ float red[8][OUTC];
    int lane = tid & 31, wp = tid >> 5;
    if (lane == 0)
        #pragma unroll
        for (int n = 0; n < OUTC; n++) red[wp][n] = acc[n];
    __syncthreads();
    if (tid == 0) {
        float z[OUTC];
        #pragma unroll
        for (int n = 0; n < OUTC; n++) {
            float s = bias[n];
            #pragma unroll
            for (int w8 = 0; w8 < 8; w8++) s += red[w8][n];
            z[n] = s;
        }
        float m = z[0];
        #pragma unroll
        for (int n = 1; n < OUTC; n++) m = fmaxf(m, z[n]);
        float se = 0.f;
        #pragma unroll
        for (int n = 0; n < OUTC; n++) se += expf(z[n] - m);
        float l = m + logf(se);
        #pragma unroll
        for (int n = 0; n < OUTC; n++) outlp[b * OUTC + n] = z[n] - l;
    }
}

// ---------------- launcher --------------------------------------------------
extern "C" void kernel_launch(void* const* d_in, const int* in_sizes, int n_in,
                              void* d_out, int out_size) {
    const float* x_in   = (const float*)d_in[0];
    const float* L_vals = (const float*)d_in[1];
    const float* cl1_w  = (const float*)d_in[2];
    const float* cl1_b  = (const float*)d_in[3];
    const float* fc1_w  = (const float*)d_in[4];
    const float* fc1_b  = (const float*)d_in[5];
    const float* fc2_w  = (const float*)d_in[6];
    const float* fc2_b  = (const float*)d_in[7];
    const float* fc3_w  = (const float*)d_in[8];
    const float* fc3_b  = (const float*)d_in[9];
    const float* nn1_w  = (const float*)d_in[10];
    const float* nn1_b  = (const float*)d_in[11];
    const float* nn2_w  = (const float*)d_in[12];
    const float* nn2_b  = (const float*)d_in[13];
    const float* sum2_w = (const float*)d_in[14];
    const float* sum2_b = (const float*)d_in[15];
    const int*   L_rows = (const int*)d_in[16];
    const int*   L_cols = (const int*)d_in[17];

    float* out = (float*)d_out;
    float* out_dec = out;                       // [64][16384]
    float* out_hid = out + (size_t)Bn * Vn;     // [64][512]
    float* out_lp  = out_hid + Bn * FC1F;       // [64][10]

    void *p_xs, *p_pooled, *p_yuni, *p_hid, *p_xd, *p_xn1, *p_xn2, *p_rowptr;
    cudaGetSymbolAddress(&p_xs, g_xs);
    cudaGetSymbolAddress(&p_pooled, g_pooled);
    cudaGetSymbolAddress(&p_yuni, g_yuni);
    cudaGetSymbolAddress(&p_hid, g_hid);
    cudaGetSymbolAddress(&p_xd, g_xd);
    cudaGetSymbolAddress(&p_xn1, g_xn1);
    cudaGetSymbolAddress(&p_xn2, g_xn2);
    cudaGetSymbolAddress(&p_rowptr, g_rowptr);

    float* xs     = (float*)p_xs;
    float* pooled = (float*)p_pooled;
    float* yuni   = (float*)p_yuni;
    float* yfc1 = yuni + YU_FC1;
    float* ynn1 = yuni + YU_NN1;
    float* ynn2 = yuni + YU_NN2;
    float* yfc2 = yuni + YU_FC2;
    float* yfc3 = yuni + YU_FC3;
    const size_t VB = (size_t)Vn * Bn;

    // node order tuned so ncu (-s 5) profiles k_spmm #1:
    // 0 memset rowptr, 1 transpose, 2 hist, 3 scan(+cursor zero), 4 scatter, 5 spmm
    cudaMemsetAsync(p_rowptr, 0, (Vn + 1) * sizeof(int));
    k_transpose_in<<<dim3(Vn / 32, Bn / 32), dim3(32, 8)>>>(x_in, xs);
    k_hist<<<En / 256, 256>>>(L_rows);
    k_scan<<<1, 1024>>>();
    k_scatter<<<En / 256, 256>>>(L_rows, L_cols, L_vals);

    // Chebyshev recursion: xs[k] = 2 L xs[k-1] - xs[k-2]
    k_spmm<<<Vn / 8, 256>>>(xs,          xs,          xs + VB,     1.f,  0.f);
    k_spmm<<<Vn / 8, 256>>>(xs + VB,     xs,          xs + 2 * VB, 2.f, -1.f);
    k_spmm<<<Vn / 8, 256>>>(xs + 2 * VB, xs + VB,     xs + 3 * VB, 2.f, -1.f);
    k_spmm<<<Vn / 8, 256>>>(xs + 3 * VB, xs + 2 * VB, xs + 4 * VB, 2.f, -1.f);
    k_spmm<<<Vn / 8, 256>>>(xs + 4 * VB, xs + 3 * VB, xs + 5 * VB, 2.f, -1.f);

    // single zero-fill for ALL gemm outputs
    cudaMemsetAsync(p_yuni, 0, (size_t)YU_TOT * sizeof(float));

    // combine + relu + maxpool -> pooled [65536][64]
    k_chebypool<<<VG / 4, dim3(64, 4)>>>(cl1_w, cl1_b);

    // fc1 -> hidden (HMMA split-bf16, split-K 64)
    k_mmagemm<<<dim3(FC1F / 128, 64), 256>>>(pooled, fc1_w, yfc1, FC1FIN, 1024);
    k_bias_act_fc1<<<FC1F * Bn / 256, 256>>>(yfc1, fc1_b, (float*)p_hid, out_hid);

    // nn branch (input = x_in^T = xs[0])
    k_mmagemm<<<dim3(NN1F / 128, 32), 256>>>(xs, nn1_w, ynn1, Vn, 512);
    k_bias_act<<<(NN1F * Bn + 255) / 256, 256>>>(ynn1, nn1_b, (float*)p_xn1, NN1F * Bn, 1);
    k_gemm<<<dim3(NN2F / 64, 4), 256>>>((float*)p_xn1, nn2_w, ynn2, NN2F, NN1F, 256);
    k_bias_act<<<(NN2F * Bn + 255) / 256, 256>>>(ynn2, nn2_b, (float*)p_xn2, NN2F * Bn, 1);

    // decode branch
    k_gemm<<<dim3(FC2F / 64, 4), 256>>>((float*)p_hid, fc2_w, yfc2, FC2F, FC1F, 128);
    k_bias_act<<<(FC2F * Bn + 255) / 256, 256>>>(yfc2, fc2_b, (float*)p_xd, FC2F * Bn, 1);
    k_mmagemm<<<dim3(Vn / 128, 2), 256>>>((float*)p_xd, fc3_w, yfc3, FC2F, 256);
    k_fc3_out<<<dim3(Vn / 32, Bn / 32), dim3(32, 8)>>>(yfc3, fc3_b, out_dec);

    // classifier head
    k_sum2<<<Bn, 256>>>((float*)p_hid, (float*)p_xn2, sum2_w, sum2_b, out_lp);
}